// round 16
// baseline (speedup 1.0000x reference)
#include <cuda_runtime.h>
#include <cstdint>
#include <cstring>

#define NB 128
#define NPTS 16384
#define GH 128
#define GW 128
#define NV (GH*GW)
#define NPART_OUT 512
#define NTHR 512
#define EPT 32          // elements per thread
#define NPAIR 16        // float2 pairs per thread
#define NWARP (NTHR/32) // 16 warps

// Reference execution model (eager JAX + compiled lax.scan) — bitwise:
//   coords:      c(i) = rn(-0.3 + rn(i*vsz))          (eager, no fma)
//   init dist²:  rn(rn(dx*dx) + rn(dy*dy))            (eager, form0)
//   scan dist²:  fma(dx, dx, rn(dy*dy))               (fused scan body, form2)
//   d = sqrt.rn(d²); argmax in sqrt domain, first-index tie-break.
// LESSON (R15): ptxas contracts adjacent mul.rn.f32x2 + add.rn.f32x2 into
// fma.rn.f32x2 — init (form0) MUST use scalar __fmul_rn/__fadd_rn intrinsics.
// Per-warp cached (S_w, idx_w) stays valid while the warp is skipped.
// Warp-tile skip: minimal candidate over the 32x32 tile >= warp max d²
// => every fminf is a bitwise no-op => skip the whole update. Exact.

__device__ unsigned char g_occ[NB * NV];

__global__ void k_zero() {
    int i = blockIdx.x * blockDim.x + threadIdx.x;
    reinterpret_cast<uint4*>(g_occ)[i] = make_uint4(0u, 0u, 0u, 0u);
}

__global__ void k_scatter(const float* __restrict__ s) {
    int t = blockIdx.x * blockDim.x + threadIdx.x;
    if (t >= NB * NPTS) return;
    float x = s[3 * t + 0];
    float y = s[3 * t + 1];
    float nx = __fmul_rn(__fdiv_rn(__fsub_rn(x, -0.3f), 0.6f), 127.0f);
    float ny = __fmul_rn(__fdiv_rn(__fsub_rn(y, -0.3f), 0.6f), 127.0f);
    int ix = (int)rintf(nx);  ix = min(max(ix, 0), GH - 1);
    int iy = (int)rintf(ny);  iy = min(max(iy, 0), GW - 1);
    int b = t >> 14;
    g_occ[b * NV + (ix << 7) + iy] = 1;
}

__device__ __forceinline__ float coordf(int a, float vsz) {
    return __fadd_rn(-0.3f, __fmul_rn((float)a, vsz));
}

__device__ __forceinline__ unsigned redux_max_u32(unsigned v) {
    unsigned d;
    asm("redux.sync.max.u32 %0, %1, 0xffffffff;" : "=r"(d) : "r"(v));
    return d;
}
__device__ __forceinline__ unsigned redux_min_u32(unsigned v) {
    unsigned d;
    asm("redux.sync.min.u32 %0, %1, 0xffffffff;" : "=r"(d) : "r"(v));
    return d;
}
// order-preserving float <-> u32 (no NaNs present)
__device__ __forceinline__ unsigned f2ord(float x) {
    unsigned u = __float_as_uint(x);
    return (u & 0x80000000u) ? ~u : (u | 0x80000000u);
}
__device__ __forceinline__ float ord2f(unsigned o) {
    unsigned u = (o & 0x80000000u) ? (o ^ 0x80000000u) : ~o;
    return __uint_as_float(u);
}

// packed square-fma: one FFMA2, no mul+add pair => no contraction hazard
__device__ __forceinline__ float2 f2_fma(float2 a, float2 b, float2 c) {
    unsigned long long ua, ub, uc, ud;
    memcpy(&ua, &a, 8); memcpy(&ub, &b, 8); memcpy(&uc, &c, 8);
    asm("fma.rn.f32x2 %0, %1, %2, %3;" : "=l"(ud) : "l"(ua), "l"(ub), "l"(uc));
    float2 d; memcpy(&d, &ud, 8); return d;
}
__device__ __forceinline__ float2 f2_add(float2 a, float2 b) {
    unsigned long long ua, ub, ud;
    memcpy(&ua, &a, 8); memcpy(&ub, &b, 8);
    asm("add.rn.f32x2 %0, %1, %2;" : "=l"(ud) : "l"(ua), "l"(ub));
    float2 d; memcpy(&d, &ud, 8); return d;
}

__global__ void __launch_bounds__(NTHR, 1) k_fps(
    const float* __restrict__ action,
    const float* __restrict__ cam,
    const float* __restrict__ wv,
    float* __restrict__ out)
{
    __shared__ unsigned sbuf[2][NWARP];  // per-warp ord(S) (double-buffered)
    __shared__ int      ibuf[2][NWARP];  // per-warp winner index
    __shared__ float    s_bias;
    __shared__ int      s_first;

    const int tid  = threadIdx.x;
    const int lane = tid & 31;
    const int wid  = tid >> 5;
    const int b    = blockIdx.x;
    const float vsz = __fdiv_rn(0.6f, 127.0f);
    const float NEG_INF = __int_as_float(0xFF800000);
    const float POS_INF = __int_as_float(0x7F800000);
    const int   BIGIDX  = 0x7FFFFFFF;

    // ---- per-batch bias: M = T_gl @ E; only its sign margin matters --------
    if (tid == 0) {
        const float tg[3] = {1.0f, -1.0f, -1.0f};
        float a0 = action[b * 4 + 0], a1 = action[b * 4 + 1];
        float a2 = action[b * 4 + 2], a3 = action[b * 4 + 3];
        float bias = 0.0f;
        #pragma unroll
        for (int r = 0; r < 3; r++) {
            float m0 = tg[r] * cam[r * 4 + 0];
            float m2 = tg[r] * cam[r * 4 + 2];
            float m3 = tg[r] * cam[r * 4 + 3];
            float s3 = (m0 * a0 + m2 * (-a1) + m3) / 24.0f;
            float e3 = (m0 * a2 + m2 * (-a3) + m3) / 24.0f;
            bias += wv[r] * s3 + wv[3 + r] * e3;
        }
        s_bias  = bias;
        s_first = BIGIDX;
    }
    __syncthreads();
    const float bias = s_bias;
    const bool mOcc = (__fadd_rn(2.0f, bias) >= 0.0f);
    const bool mEmp = (__fsub_rn(bias, 2.0f) >= 0.0f);

    // ---- element mapping: warp owns a 32x32 tile ----------------------------
    const int i0    = tid >> 7;          // 0..3 (warp-uniform)
    const int jj    = tid & 127;         // this thread's column
    const int rbase = i0 * 32;           // warp rows  [rbase, rbase+31]
    const int jbase = (wid & 3) * 32;    // warp cols  [jbase, jbase+31]
    const int vbase = i0 * 4096 + jj;    // voxel index base (+ k*128)

    // iteration-invariant row coordinates, packed in pairs
    float2 cr2[NPAIR];
    #pragma unroll
    for (int q = 0; q < NPAIR; q++)
        cr2[q] = make_float2(coordf(rbase + 2*q, vsz), coordf(rbase + 2*q + 1, vsz));
    const float cj = coordf(jj, vsz);

    // ---- init mask / d² state; first masked voxel ---------------------------
    float2 dsq2[NPAIR];
    int firstM = BIGIDX;
    #pragma unroll
    for (int q = 0; q < NPAIR; q++) {
        int v0 = vbase + (2*q) * 128;
        int v1 = v0 + 128;
        bool mx_ = g_occ[b * NV + v0] ? mOcc : mEmp;
        bool my_ = g_occ[b * NV + v1] ? mOcc : mEmp;
        dsq2[q].x = mx_ ? POS_INF : NEG_INF;
        dsq2[q].y = my_ ? POS_INF : NEG_INF;
        if (mx_ && firstM == BIGIDX) firstM = v0;
        if (my_ && firstM == BIGIDX) firstM = v1;
    }
    if (firstM != BIGIDX) atomicMin(&s_first, firstM);
    __syncthreads();
    int startv = s_first;
    if (startv == BIGIDX) {
        startv = 0;
        #pragma unroll
        for (int q = 0; q < NPAIR; q++) dsq2[q] = make_float2(POS_INF, POS_INF);
    }
    if (tid == 0) {
        size_t o3 = (size_t)b * NPART_OUT * 3;
        out[o3 + 0] = coordf(startv >> 7, vsz);
        out[o3 + 1] = coordf(startv & 127, vsz);
        out[o3 + 2] = 0.745f;
    }

    int fpv = startv;
    float m_w = NEG_INF;       // warp max of dsq (uniform)
    unsigned ordS_w = f2ord(NEG_INF);
    int idx_w = BIGIDX;

    for (int it = 1; it < NPART_OUT; it++) {
        const int pi = fpv >> 7, pj = fpv & 127;
        const float cpi = coordf(pi, vsz);
        const float cpj = coordf(pj, vsz);
        const float dyj = __fsub_rn(cj, cpj);
        const float cy  = __fmul_rn(dyj, dyj);

        bool active;
        if (it == 1) {
            active = true;
        } else {
            int rn_ = min(max(pi, rbase), rbase + 31);
            int jn_ = min(max(pj, jbase), jbase + 31);
            float dxn = __fsub_rn(coordf(rn_, vsz), cpi);
            float dyn = __fsub_rn(coordf(jn_, vsz), cpj);
            float svmin = __fmaf_rn(dxn, dxn, __fmul_rn(dyn, dyn));
            active = (svmin < m_w);
        }

        if (active) {                    // warp-uniform branch
            float m0 = NEG_INF, m1 = NEG_INF, m2a = NEG_INF, m3 = NEG_INF;
            if (it == 1) {
                // form0 init: SCALAR intrinsics only (f32x2 mul+add gets
                // contracted to fma by ptxas — proven by R15's failure)
                #pragma unroll
                for (int q = 0; q < NPAIR; q++) {
                    float d0 = __fsub_rn(cr2[q].x, cpi);
                    float d1 = __fsub_rn(cr2[q].y, cpi);
                    float s0 = __fadd_rn(__fmul_rn(d0, d0), cy);
                    float s1 = __fadd_rn(__fmul_rn(d1, d1), cy);
                    if (q & 1) {
                        dsq2[q].x = fminf(dsq2[q].x, s0);  m2a = fmaxf(m2a, dsq2[q].x);
                        dsq2[q].y = fminf(dsq2[q].y, s1);  m3  = fmaxf(m3,  dsq2[q].y);
                    } else {
                        dsq2[q].x = fminf(dsq2[q].x, s0);  m0 = fmaxf(m0, dsq2[q].x);
                        dsq2[q].y = fminf(dsq2[q].y, s1);  m1 = fmaxf(m1, dsq2[q].y);
                    }
                }
            } else {
                // form2 scan body: single FFMA2 per pair (no contraction hazard)
                const float2 ncpi2 = make_float2(-cpi, -cpi);  // exact negation
                const float2 cy2   = make_float2(cy, cy);
                #pragma unroll
                for (int q = 0; q < NPAIR; q++) {
                    float2 d2 = f2_add(cr2[q], ncpi2);   // rn(cr - cpi) bitwise
                    float2 s2 = f2_fma(d2, d2, cy2);     // fma(dx,dx,cy)
                    if (q & 1) {
                        dsq2[q].x = fminf(dsq2[q].x, s2.x);  m2a = fmaxf(m2a, dsq2[q].x);
                        dsq2[q].y = fminf(dsq2[q].y, s2.y);  m3  = fmaxf(m3,  dsq2[q].y);
                    } else {
                        dsq2[q].x = fminf(dsq2[q].x, s2.x);  m0 = fmaxf(m0, dsq2[q].x);
                        dsq2[q].y = fminf(dsq2[q].y, s2.y);  m1 = fmaxf(m1, dsq2[q].y);
                    }
                }
            }
            float wm = fmaxf(fmaxf(m0, m1), fmaxf(m2a, m3));
            m_w = ord2f(redux_max_u32(f2ord(wm)));

            if (m_w >= 0.0f) {
                float S = __fsqrt_rn(m_w);
                // lane-parallel tie-window search: lanes 0..7 probe u-1-lane.
                // sqrt monotone => ok-set is a lane prefix.
                unsigned u = __float_as_uint(m_w);
                for (;;) {
                    unsigned step = (unsigned)lane + 1u;
                    bool ok = false;
                    if (lane < 8 && u >= step)
                        ok = (__fsqrt_rn(__uint_as_float(u - step)) == S);
                    unsigned mask = __ballot_sync(0xFFFFFFFFu, ok) & 0xFFu;
                    if (mask == 0xFFu) { u -= 8u; continue; }   // window > 8 (rare)
                    u -= (unsigned)(__ffs(~(int)mask) - 1);     // prefix run length
                    break;
                }
                float L = __uint_as_float(u);

                int b0 = BIGIDX, b1 = BIGIDX, b2 = BIGIDX, b3 = BIGIDX;
                #pragma unroll
                for (int q = 0; q < NPAIR; q++) {
                    int v0 = vbase + (2*q) * 128;
                    if (q & 1) {
                        b2 = min(b2, (dsq2[q].x >= L) ? v0 : BIGIDX);
                        b3 = min(b3, (dsq2[q].y >= L) ? (v0 + 128) : BIGIDX);
                    } else {
                        b0 = min(b0, (dsq2[q].x >= L) ? v0 : BIGIDX);
                        b1 = min(b1, (dsq2[q].y >= L) ? (v0 + 128) : BIGIDX);
                    }
                }
                idx_w = (int)redux_min_u32((unsigned)min(min(b0, b1), min(b2, b3)));
                ordS_w = f2ord(S);
            } else {
                ordS_w = f2ord(NEG_INF);   // all-unmasked warp: never wins
                idx_w = BIGIDX;
            }
        }

        const int p = it & 1;
        if (lane == 0) { sbuf[p][wid] = ordS_w; ibuf[p][wid] = idx_w; }
        __syncthreads();                           // the ONLY barrier

        // ---- block winner: max S then min idx, via 2 redux ------------------
        unsigned us = sbuf[p][lane & (NWARP - 1)];
        int      ui = ibuf[p][lane & (NWARP - 1)];
        unsigned Smax = redux_max_u32(us);
        int cand = (us == Smax) ? ui : BIGIDX;
        fpv = (int)redux_min_u32((unsigned)cand);

        if (tid == 0) {
            size_t o3 = ((size_t)b * NPART_OUT + it) * 3;
            out[o3 + 0] = coordf(fpv >> 7, vsz);
            out[o3 + 1] = coordf(fpv & 127, vsz);
            out[o3 + 2] = 0.745f;
        }
    }
}

// ---------------------------------------------------------------------------
// Inputs bound BY ELEMENT COUNT (all five sizes distinct):
//   s_cur 6291456 | action 512 | cam 16 | w_action 6 | n_particles 1 (unused)
// Output: f32 (128, 512, 3)
// ---------------------------------------------------------------------------
extern "C" void kernel_launch(void* const* d_in, const int* in_sizes, int n_in,
                              void* d_out, int out_size) {
    const float* s_cur  = nullptr;
    const float* action = nullptr;
    const float* cam    = nullptr;
    const float* wv     = nullptr;
    for (int i = 0; i < n_in; i++) {
        switch (in_sizes[i]) {
            case NB * NPTS * 3: s_cur  = (const float*)d_in[i]; break;
            case NB * 4:        action = (const float*)d_in[i]; break;
            case 16:            cam    = (const float*)d_in[i]; break;
            case 6:             wv     = (const float*)d_in[i]; break;
            default: break;
        }
    }
    if (!s_cur)  s_cur  = (const float*)d_in[0];
    if (!action) action = (const float*)d_in[1];
    if (!cam)    cam    = (const float*)d_in[2];
    if (!wv)     wv     = (const float*)d_in[3];
    float* out = (float*)d_out;

    k_zero<<<(NB * NV / 16) / 256, 256>>>();
    k_scatter<<<(NB * NPTS) / 256, 256>>>(s_cur);
    k_fps<<<NB, NTHR>>>(action, cam, wv, out);
}

// round 17
// speedup vs baseline: 1.4701x; 1.4701x over previous
#include <cuda_runtime.h>
#include <cstdint>

#define NB 128
#define NPTS 16384
#define GH 128
#define GW 128
#define NV (GH*GW)
#define NPART_OUT 512
#define NTHR 512
#define EPT 32          // elements per thread
#define NWARP (NTHR/32) // 16 warps

// Reference execution model (eager JAX + compiled lax.scan) — bitwise:
//   coords:      c(i) = rn(-0.3 + rn(i*vsz))          (eager, no fma)
//   init dist²:  rn(rn(dx*dx) + rn(dy*dy))            (eager, form0)
//   scan dist²:  fma(dx, dx, rn(dy*dy))               (fused scan body, form2)
//   d = sqrt.rn(d²); argmax in sqrt domain, first-index tie-break.
// Sqrt-free argmax: tie-window [L, m_w] = preimage of S under monotone
// sqrt_rn; first index with d² >= L == reference argmax. Exact.
// LESSONS: (R15) ptxas contracts mul.rn.f32x2+add.rn.f32x2 -> fma;
//          (R16) f32x2-packed live state causes pack/unpack MOV churn.
//          => ALL state math stays scalar intrinsics.
// Occupancy via generation tag: scatter writes g_gen, fps tests ==g_gen.
// Bit-identical mask, no clearing kernel needed.

__device__ unsigned g_gen = 0;
__device__ unsigned g_occ_tag[NB * NV];   // zero-initialized at module load

__global__ void k_bump() { g_gen++; }

__global__ void k_scatter(const float* __restrict__ s) {
    int t = blockIdx.x * blockDim.x + threadIdx.x;
    if (t >= NB * NPTS) return;
    const unsigned gen = g_gen;
    float x = s[3 * t + 0];
    float y = s[3 * t + 1];
    float nx = __fmul_rn(__fdiv_rn(__fsub_rn(x, -0.3f), 0.6f), 127.0f);
    float ny = __fmul_rn(__fdiv_rn(__fsub_rn(y, -0.3f), 0.6f), 127.0f);
    int ix = (int)rintf(nx);  ix = min(max(ix, 0), GH - 1);
    int iy = (int)rintf(ny);  iy = min(max(iy, 0), GW - 1);
    int b = t >> 14;
    g_occ_tag[b * NV + (ix << 7) + iy] = gen;
}

__device__ __forceinline__ float coordf(int a, float vsz) {
    return __fadd_rn(-0.3f, __fmul_rn((float)a, vsz));
}

__device__ __forceinline__ unsigned redux_max_u32(unsigned v) {
    unsigned d;
    asm("redux.sync.max.u32 %0, %1, 0xffffffff;" : "=r"(d) : "r"(v));
    return d;
}
__device__ __forceinline__ unsigned redux_min_u32(unsigned v) {
    unsigned d;
    asm("redux.sync.min.u32 %0, %1, 0xffffffff;" : "=r"(d) : "r"(v));
    return d;
}
// order-preserving float <-> u32 (no NaNs present)
__device__ __forceinline__ unsigned f2ord(float x) {
    unsigned u = __float_as_uint(x);
    return (u & 0x80000000u) ? ~u : (u | 0x80000000u);
}
__device__ __forceinline__ float ord2f(unsigned o) {
    unsigned u = (o & 0x80000000u) ? (o ^ 0x80000000u) : ~o;
    return __uint_as_float(u);
}

__global__ void __launch_bounds__(NTHR, 1) k_fps(
    const float* __restrict__ action,
    const float* __restrict__ cam,
    const float* __restrict__ wv,
    float* __restrict__ out)
{
    __shared__ unsigned sbuf[2][NWARP];  // per-warp ord(S), double-buffered
    __shared__ int      ibuf[2][NWARP];  // per-warp winner index
    __shared__ float    s_bias;
    __shared__ int      s_first;

    const int tid  = threadIdx.x;
    const int lane = tid & 31;
    const int wid  = tid >> 5;
    const int b    = blockIdx.x;
    const float vsz = __fdiv_rn(0.6f, 127.0f);
    const float NEG_INF = __int_as_float(0xFF800000);
    const float POS_INF = __int_as_float(0x7F800000);
    const int   BIGIDX  = 0x7FFFFFFF;

    // ---- per-batch bias: M = T_gl @ E; only its sign margin matters --------
    if (tid == 0) {
        const float tg[3] = {1.0f, -1.0f, -1.0f};
        float a0 = action[b * 4 + 0], a1 = action[b * 4 + 1];
        float a2 = action[b * 4 + 2], a3 = action[b * 4 + 3];
        float bias = 0.0f;
        #pragma unroll
        for (int r = 0; r < 3; r++) {
            float m0 = tg[r] * cam[r * 4 + 0];
            float m2 = tg[r] * cam[r * 4 + 2];
            float m3 = tg[r] * cam[r * 4 + 3];
            float s3 = (m0 * a0 + m2 * (-a1) + m3) / 24.0f;
            float e3 = (m0 * a2 + m2 * (-a3) + m3) / 24.0f;
            bias += wv[r] * s3 + wv[3 + r] * e3;
        }
        s_bias  = bias;
        s_first = BIGIDX;
    }
    __syncthreads();
    const float bias = s_bias;
    const bool mOcc = (__fadd_rn(2.0f, bias) >= 0.0f);
    const bool mEmp = (__fsub_rn(bias, 2.0f) >= 0.0f);

    // ---- element mapping: warp owns a 32x32 tile ----------------------------
    const int i0    = tid >> 7;          // 0..3 (warp-uniform)
    const int jj    = tid & 127;         // this thread's column
    const int rbase = i0 * 32;           // warp rows  [rbase, rbase+31]
    const int jbase = (wid & 3) * 32;    // warp cols  [jbase, jbase+31]
    const int vbase = i0 * 4096 + jj;    // voxel index base (+ k*128)

    // iteration-invariant row coordinates in registers
    float cr[EPT];
    #pragma unroll
    for (int k = 0; k < EPT; k++) cr[k] = coordf(rbase + k, vsz);
    const float cj = coordf(jj, vsz);

    // ---- init mask / d² state; first masked voxel ---------------------------
    const unsigned gen = g_gen;
    float dsq[EPT];
    int firstM = BIGIDX;
    #pragma unroll
    for (int k = 0; k < EPT; k++) {
        int v = vbase + k * 128;
        bool m = (g_occ_tag[b * NV + v] == gen) ? mOcc : mEmp;
        dsq[k] = m ? POS_INF : NEG_INF;
        if (m && firstM == BIGIDX) firstM = v;
    }
    if (firstM != BIGIDX) atomicMin(&s_first, firstM);
    __syncthreads();
    int startv = s_first;
    if (startv == BIGIDX) {
        startv = 0;
        #pragma unroll
        for (int k = 0; k < EPT; k++) dsq[k] = POS_INF;
    }
    if (tid == 0) {
        size_t o3 = (size_t)b * NPART_OUT * 3;
        out[o3 + 0] = coordf(startv >> 7, vsz);
        out[o3 + 1] = coordf(startv & 127, vsz);
        out[o3 + 2] = 0.745f;
    }

    int fpv = startv;
    float m_w = NEG_INF;       // warp max of dsq (uniform)
    unsigned ordS_w = f2ord(NEG_INF);
    int idx_w = BIGIDX;

    for (int it = 1; it < NPART_OUT; it++) {
        const int pi = fpv >> 7, pj = fpv & 127;
        const float cpi = coordf(pi, vsz);
        const float cpj = coordf(pj, vsz);
        const float dyj = __fsub_rn(cj, cpj);
        const float cy  = __fmul_rn(dyj, dyj);

        bool active;
        if (it == 1) {
            active = true;
        } else {
            // warp-tile skip: minimal candidate over the 32x32 tile (uniform)
            int rn_ = min(max(pi, rbase), rbase + 31);
            int jn_ = min(max(pj, jbase), jbase + 31);
            float dxn = __fsub_rn(coordf(rn_, vsz), cpi);
            float dyn = __fsub_rn(coordf(jn_, vsz), cpj);
            float svmin = __fmaf_rn(dxn, dxn, __fmul_rn(dyn, dyn));
            active = (svmin < m_w);
        }

        if (active) {                    // warp-uniform branch
            float m0 = NEG_INF, m1 = NEG_INF, m2a = NEG_INF, m3 = NEG_INF;
            if (it == 1) {
                // form0 (eager init): rn(rn(dx*dx) + cy) — scalar only
                #pragma unroll
                for (int k = 0; k < EPT; k += 4) {
                    float d0 = __fsub_rn(cr[k+0], cpi);
                    float d1 = __fsub_rn(cr[k+1], cpi);
                    float d2 = __fsub_rn(cr[k+2], cpi);
                    float d3 = __fsub_rn(cr[k+3], cpi);
                    float s0 = __fadd_rn(__fmul_rn(d0, d0), cy);
                    float s1 = __fadd_rn(__fmul_rn(d1, d1), cy);
                    float s2 = __fadd_rn(__fmul_rn(d2, d2), cy);
                    float s3 = __fadd_rn(__fmul_rn(d3, d3), cy);
                    dsq[k+0] = fminf(dsq[k+0], s0);  m0 = fmaxf(m0, dsq[k+0]);
                    dsq[k+1] = fminf(dsq[k+1], s1);  m1 = fmaxf(m1, dsq[k+1]);
                    dsq[k+2] = fminf(dsq[k+2], s2);  m2a = fmaxf(m2a, dsq[k+2]);
                    dsq[k+3] = fminf(dsq[k+3], s3);  m3 = fmaxf(m3, dsq[k+3]);
                }
            } else {
                // form2 (scan body): fma(dx,dx, cy) — scalar only
                #pragma unroll
                for (int k = 0; k < EPT; k += 4) {
                    float d0 = __fsub_rn(cr[k+0], cpi);
                    float d1 = __fsub_rn(cr[k+1], cpi);
                    float d2 = __fsub_rn(cr[k+2], cpi);
                    float d3 = __fsub_rn(cr[k+3], cpi);
                    float s0 = __fmaf_rn(d0, d0, cy);
                    float s1 = __fmaf_rn(d1, d1, cy);
                    float s2 = __fmaf_rn(d2, d2, cy);
                    float s3 = __fmaf_rn(d3, d3, cy);
                    dsq[k+0] = fminf(dsq[k+0], s0);  m0 = fmaxf(m0, dsq[k+0]);
                    dsq[k+1] = fminf(dsq[k+1], s1);  m1 = fmaxf(m1, dsq[k+1]);
                    dsq[k+2] = fminf(dsq[k+2], s2);  m2a = fmaxf(m2a, dsq[k+2]);
                    dsq[k+3] = fminf(dsq[k+3], s3);  m3 = fmaxf(m3, dsq[k+3]);
                }
            }
            float wm = fmaxf(fmaxf(m0, m1), fmaxf(m2a, m3));
            m_w = ord2f(redux_max_u32(f2ord(wm)));

            // per-warp sqrt key + tie-window lower bound + min index
            if (m_w >= 0.0f) {
                float S = __fsqrt_rn(m_w);
                unsigned u = __float_as_uint(m_w);
                #pragma unroll 1
                while (u > 0u && __fsqrt_rn(__uint_as_float(u - 1u)) == S) u--;
                float L = __uint_as_float(u);
                int b0 = BIGIDX, b1 = BIGIDX, b2 = BIGIDX, b3 = BIGIDX;
                #pragma unroll
                for (int k = 0; k < EPT; k += 4) {
                    b0 = min(b0, (dsq[k+0] >= L) ? (vbase + (k+0) * 128) : BIGIDX);
                    b1 = min(b1, (dsq[k+1] >= L) ? (vbase + (k+1) * 128) : BIGIDX);
                    b2 = min(b2, (dsq[k+2] >= L) ? (vbase + (k+2) * 128) : BIGIDX);
                    b3 = min(b3, (dsq[k+3] >= L) ? (vbase + (k+3) * 128) : BIGIDX);
                }
                idx_w = (int)redux_min_u32((unsigned)min(min(b0, b1), min(b2, b3)));
                ordS_w = f2ord(S);
            } else {
                ordS_w = f2ord(NEG_INF);   // all-unmasked warp: never wins
                idx_w = BIGIDX;
            }
        }

        const int p = it & 1;
        if (lane == 0) { sbuf[p][wid] = ordS_w; ibuf[p][wid] = idx_w; }
        __syncthreads();                           // the ONLY barrier

        // ---- block winner: max S (redux), tie -> min idx (redux) ------------
        unsigned us = sbuf[p][lane & (NWARP - 1)];
        int      ui = ibuf[p][lane & (NWARP - 1)];
        unsigned Smax = redux_max_u32(us);
        int cand = (us == Smax) ? ui : BIGIDX;
        fpv = (int)redux_min_u32((unsigned)cand);

        if (tid == 0) {
            size_t o3 = ((size_t)b * NPART_OUT + it) * 3;
            out[o3 + 0] = coordf(fpv >> 7, vsz);
            out[o3 + 1] = coordf(fpv & 127, vsz);
            out[o3 + 2] = 0.745f;
        }
    }
}

// ---------------------------------------------------------------------------
// Inputs bound BY ELEMENT COUNT (all five sizes distinct):
//   s_cur 6291456 | action 512 | cam 16 | w_action 6 | n_particles 1 (unused)
// Output: f32 (128, 512, 3)
// Launch order (bump, scatter, fps) also lands ncu's "-s 5 -c 1" on k_fps.
// ---------------------------------------------------------------------------
extern "C" void kernel_launch(void* const* d_in, const int* in_sizes, int n_in,
                              void* d_out, int out_size) {
    const float* s_cur  = nullptr;
    const float* action = nullptr;
    const float* cam    = nullptr;
    const float* wv     = nullptr;
    for (int i = 0; i < n_in; i++) {
        switch (in_sizes[i]) {
            case NB * NPTS * 3: s_cur  = (const float*)d_in[i]; break;
            case NB * 4:        action = (const float*)d_in[i]; break;
            case 16:            cam    = (const float*)d_in[i]; break;
            case 6:             wv     = (const float*)d_in[i]; break;
            default: break;
        }
    }
    if (!s_cur)  s_cur  = (const float*)d_in[0];
    if (!action) action = (const float*)d_in[1];
    if (!cam)    cam    = (const float*)d_in[2];
    if (!wv)     wv     = (const float*)d_in[3];
    float* out = (float*)d_out;

    k_bump<<<1, 1>>>();
    k_scatter<<<(NB * NPTS) / 256, 256>>>(s_cur);
    k_fps<<<NB, NTHR>>>(action, cam, wv, out);
}